// round 14
// baseline (speedup 1.0000x reference)
#include <cuda_runtime.h>
#include <cuda_bf16.h>
#include <cstdint>

// ---------------- problem constants ----------------
static constexpr int Bq  = 4;
static constexpr int Lq  = 4096;
static constexpr int Dq  = 1024;
static constexpr int Hq  = 4;
static constexpr int DK  = 256;
static constexpr int Cq  = 64;
static constexpr int NCq = 64;
static constexpr int KSq = 4;
static constexpr int FH  = 128;           // DK/2
static constexpr int BL  = Bq * Lq;       // 16384
static constexpr int BH  = Bq * Hq;       // 16
static constexpr int CHUNKS = BH * NCq;   // 1024
static constexpr int CD  = Cq * DK;       // 16384

// ---------------- scratch (static device globals; no allocation) ----------------
__device__ float g_Pq[BL * Dq];
__device__ float g_Pk[BL * Dq];
__device__ float g_Pv[BL * Dq];
__device__ float g_Pg[BL * Dq];
__device__ float g_beta[BL * Hq];
__device__ float g_q[BL * Dq];   // chunk layout: ((b*H+h)*NC+n)*C*DK + c*DK + dk
__device__ float g_k[BL * Dq];
__device__ float g_v[BL * Dq];
__device__ float g_w[BL * Dq];
__device__ float g_u[BL * Dq];
__device__ float g_attn[CHUNKS * Cq * Cq];
__device__ float g_psi[CHUNKS];
__device__ float g_o[BL * Dq];   // chunk layout
__device__ float g_og[BL * Dq];  // (b,l,d) layout, gated

__device__ __forceinline__ float sigf(float x) { return 1.f / (1.f + expf(-x)); }

// ---------------- generic SGEMM: C = A[MxK] * B[KxN], row-major ----------------
// BM=BN=128, BK=8, 256 threads, 8x8 per thread. M%128==0, N%128==0, K%8==0.
__global__ __launch_bounds__(256) void sgemm_kernel(
    const float* __restrict__ A, const float* __restrict__ B,
    float* __restrict__ Cm, int M, int N, int K)
{
    __shared__ float As[8][132];
    __shared__ float Bs[8][128];
    const int bx = blockIdx.x;   // N tile
    const int by = blockIdx.y;   // M tile
    const int tid = threadIdx.x;
    const int tx = tid & 15;     // 0..15
    const int ty = tid >> 4;     // 0..15
    float acc[8][8];
    #pragma unroll
    for (int i = 0; i < 8; i++)
        #pragma unroll
        for (int j = 0; j < 8; j++) acc[i][j] = 0.f;

    const int aRow  = tid >> 1;        // 0..127
    const int aCol4 = (tid & 1) * 4;   // 0 or 4
    const int bRow  = tid >> 5;        // 0..7
    const int bCol4 = (tid & 31) * 4;  // 0..124

    const float* Ablk = A + (size_t)(by * 128) * K;
    const float* Bblk = B + bx * 128;

    for (int k0 = 0; k0 < K; k0 += 8) {
        float4 av = *(const float4*)(Ablk + (size_t)aRow * K + k0 + aCol4);
        As[aCol4 + 0][aRow] = av.x;
        As[aCol4 + 1][aRow] = av.y;
        As[aCol4 + 2][aRow] = av.z;
        As[aCol4 + 3][aRow] = av.w;
        *(float4*)&Bs[bRow][bCol4] = *(const float4*)(Bblk + (size_t)(k0 + bRow) * N + bCol4);
        __syncthreads();
        #pragma unroll
        for (int kk = 0; kk < 8; kk++) {
            float4 a0 = *(float4*)&As[kk][ty * 8];
            float4 a1 = *(float4*)&As[kk][ty * 8 + 4];
            float4 b0 = *(float4*)&Bs[kk][tx * 8];
            float4 b1 = *(float4*)&Bs[kk][tx * 8 + 4];
            float ar[8] = {a0.x,a0.y,a0.z,a0.w,a1.x,a1.y,a1.z,a1.w};
            float br[8] = {b0.x,b0.y,b0.z,b0.w,b1.x,b1.y,b1.z,b1.w};
            #pragma unroll
            for (int i = 0; i < 8; i++)
                #pragma unroll
                for (int j = 0; j < 8; j++) acc[i][j] += ar[i] * br[j];
        }
        __syncthreads();
    }
    float* Cblk = Cm + (size_t)(by * 128) * N + bx * 128;
    #pragma unroll
    for (int i = 0; i < 8; i++) {
        #pragma unroll
        for (int j = 0; j < 8; j += 4) {
            float4 v = make_float4(acc[i][j], acc[i][j+1], acc[i][j+2], acc[i][j+3]);
            *(float4*)(Cblk + (size_t)(ty * 8 + i) * N + tx * 8 + j) = v;
        }
    }
}

// ---------------- beta = sigmoid(x @ Wb), (BL, H) ----------------
__global__ __launch_bounds__(128) void beta_kernel(
    const float* __restrict__ x, const float* __restrict__ Wb)
{
    int r = blockIdx.x;
    int lane = threadIdx.x & 31;
    int h    = threadIdx.x >> 5;   // 4 warps -> 4 heads
    const float* xr = x + (size_t)r * Dq;
    float s = 0.f;
    for (int d = lane; d < Dq; d += 32) s += xr[d] * Wb[d * Hq + h];
    #pragma unroll
    for (int o = 16; o; o >>= 1) s += __shfl_xor_sync(~0u, s, o);
    if (lane == 0) g_beta[(size_t)r * Hq + h] = sigf(s);
}

// ---------------- conv + silu + l2norm(q,k) + chunk-layout scatter ----------------
__global__ __launch_bounds__(256) void conv_kernel(
    const float* __restrict__ cq, const float* __restrict__ ck, const float* __restrict__ cv)
{
    int r = blockIdx.x;
    int b = r >> 12;          // L = 4096
    int l = r & 4095;
    int t = threadIdx.x;      // 0..255 = dk
    __shared__ float sums[2][Hq];
    if (t < 8) ((float*)sums)[t] = 0.f;
    __syncthreads();

    float qv[4], kv[4], vv[4];
    #pragma unroll
    for (int i = 0; i < 4; i++) {          // head i
        int d = i * 256 + t;
        float aq = 0.f, ak = 0.f, av = 0.f;
        #pragma unroll
        for (int j = 0; j < KSq; j++) {
            int ll = l - 2 + j;
            if ((unsigned)ll < (unsigned)Lq) {
                size_t idx = (size_t)(b * Lq + ll) * Dq + d;
                aq += g_Pq[idx] * cq[d * KSq + j];
                ak += g_Pk[idx] * ck[d * KSq + j];
                av += g_Pv[idx] * cv[d * KSq + j];
            }
        }
        qv[i] = aq * sigf(aq);
        kv[i] = ak * sigf(ak);
        vv[i] = av * sigf(av);
        float sq = qv[i] * qv[i];
        float sk = kv[i] * kv[i];
        #pragma unroll
        for (int o = 16; o; o >>= 1) {
            sq += __shfl_xor_sync(~0u, sq, o);
            sk += __shfl_xor_sync(~0u, sk, o);
        }
        if ((t & 31) == 0) {
            atomicAdd(&sums[0][i], sq);
            atomicAdd(&sums[1][i], sk);
        }
    }
    __syncthreads();
    int n = l >> 6, c = l & 63;
    #pragma unroll
    for (int i = 0; i < 4; i++) {
        float rq = rsqrtf(sums[0][i] + 1e-6f);
        float rk = rsqrtf(sums[1][i] + 1e-6f);
        size_t o = ((size_t)((b * Hq + i) * NCq + n) * Cq + c) * DK + t;
        g_q[o] = qv[i] * rq;
        g_k[o] = kv[i] * rk;
        g_v[o] = vv[i];
    }
}

// ---------------- per-chunk: A, T=(I+A)^-1, w, u, attn, flux MLP -> psi ----------------
static constexpr int DKP = 257;  // padded row (257 % 32 == 1 -> conflict-free)
static constexpr int SMEM_CHUNK = (2 * 64 * DKP + 2 * 64 * 65 + 64 + 520) * 4;  // 167200 B

__global__ __launch_bounds__(256) void chunk_kernel(
    const float* __restrict__ Wbil, const float* __restrict__ temp,
    const float* __restrict__ fw1, const float* __restrict__ fb1,
    const float* __restrict__ fw2, const float* __restrict__ fb2)
{
    int cid = blockIdx.x;
    int n  = cid % NCq;
    int bh = cid / NCq;
    int h  = bh % Hq;
    int b  = bh / Hq;
    int t  = threadIdx.x;

    extern __shared__ float sm[];
    float* sk    = sm;                     // 64 * DKP
    float* sq    = sk + 64 * DKP;          // 64 * DKP
    float* sT    = sq + 64 * DKP;          // 64 * 65
    float* sA    = sT + 64 * 65;           // 64 * 65
    float* sbeta = sA + 64 * 65;           // 64
    float* sred  = sbeta + 64;             // 520
    __shared__ float warp_part[8];

    size_t base = (size_t)cid * CD;
    for (int i = t; i < CD; i += 256) {
        int c = i >> 8, d = i & 255;
        sk[c * DKP + d] = g_k[base + i];
        sq[c * DKP + d] = g_q[base + i];
    }
    if (t < 64) sbeta[t] = g_beta[(size_t)(b * Lq + n * Cq + t) * Hq + h];
    __syncthreads();

    // A[i][j] = beta_i * (k_i . k_j), strictly lower
    for (int p = t; p < 64 * 64; p += 256) {
        int i = p >> 6, j = p & 63;
        float val = 0.f;
        if (j < i) {
            const float* ki = sk + i * DKP;
            const float* kj = sk + j * DKP;
            #pragma unroll 8
            for (int d = 0; d < 256; d++) val += ki[d] * kj[d];
            val *= sbeta[i];
        }
        sA[i * 65 + j] = val;
    }
    __syncthreads();

    // T = (I + A)^-1 by forward substitution (unit lower triangular)
    for (int p = t; p < 64 * 64; p += 256) {
        int i = p >> 6, j = p & 63;
        sT[i * 65 + j] = (i == j) ? 1.f : 0.f;
    }
    __syncthreads();
    for (int i = 1; i < 64; i++) {
        if (t < i) {
            float s = 0.f;
            for (int m = t; m < i; m++) s += sA[i * 65 + m] * sT[m * 65 + t];
            sT[i * 65 + t] = -s;
        }
        __syncthreads();
    }

    // attn = (q k^T) * causal -> global (used by scan)
    for (int p = t; p < 64 * 64; p += 256) {
        int i = p >> 6, j = p & 63;
        float val = 0.f;
        if (j <= i) {
            const float* qi = sq + i * DKP;
            const float* kj = sk + j * DKP;
            #pragma unroll 8
            for (int d = 0; d < 256; d++) val += qi[d] * kj[d];
        }
        g_attn[(size_t)cid * Cq * Cq + p] = val;
    }

    // w = T @ (beta * k)   (thread t owns column d = t)
    {
        float acc[64];
        #pragma unroll
        for (int c = 0; c < 64; c++) acc[c] = 0.f;
        for (int e = 0; e < 64; e++) {
            float kv = sbeta[e] * sk[e * DKP + t];
            #pragma unroll
            for (int c = 0; c < 64; c++) acc[c] += sT[c * 65 + e] * kv;
        }
        #pragma unroll
        for (int c = 0; c < 64; c++) g_w[base + c * DK + t] = acc[c];
    }

    // u = T @ (beta * v), keep column in registers
    float u_loc[64];
    {
        #pragma unroll
        for (int c = 0; c < 64; c++) u_loc[c] = 0.f;
        for (int e = 0; e < 64; e++) {
            float vv = sbeta[e] * g_v[base + e * DK + t];
            #pragma unroll
            for (int c = 0; c < 64; c++) u_loc[c] += sT[c * 65 + e] * vv;
        }
        #pragma unroll
        for (int c = 0; c < 64; c++) g_u[base + c * DK + t] = u_loc[c];
    }

    // avg_attn = sum_{c,d,v} k[c,d] Wbil[h][d,v] u[c,v] / C / temp[h]; thread t owns v=t
    float avp = 0.f;
    {
        const float* Wbh = Wbil + (size_t)h * DK * DK;
        for (int d = 0; d < 256; d++) {
            float m = 0.f;
            #pragma unroll 8
            for (int c = 0; c < 64; c++) m += sk[c * DKP + d] * u_loc[c];
            avp += m * Wbh[(size_t)d * DK + t];
        }
    }
    {
        float s = avp;
        #pragma unroll
        for (int o = 16; o; o >>= 1) s += __shfl_xor_sync(~0u, s, o);
        if ((t & 31) == 0) warp_part[t >> 5] = s;
    }
    __syncthreads();
    float avg;
    {
        float s = 0.f;
        #pragma unroll
        for (int i = 0; i < 8; i++) s += warp_part[i];
        avg = s / (float)Cq / temp[h];
    }

    // means over C
    float km = 0.f, um = 0.f;
    #pragma unroll
    for (int c = 0; c < 64; c++) { km += sk[c * DKP + t]; um += u_loc[c]; }
    km *= (1.f / 64.f); um *= (1.f / 64.f);
    sred[t] = km; sred[256 + t] = um;
    if (t == 0) sred[512] = avg;
    __syncthreads();

    // flux MLP: h1 = silu(flux @ fw1 + fb1); psi = clip(sigmoid(h1 @ fw2 + fb2))
    float h1v = 0.f;
    if (t < FH) {
        float s = fb1[t];
        for (int i = 0; i < 513; i++) s += sred[i] * fw1[i * FH + t];
        h1v = s * sigf(s);
    }
    float pp = (t < FH) ? h1v * fw2[t] : 0.f;
    #pragma unroll
    for (int o = 16; o; o >>= 1) pp += __shfl_xor_sync(~0u, pp, o);
    __syncthreads();
    if ((t & 31) == 0) warp_part[t >> 5] = pp;
    __syncthreads();
    if (t == 0) {
        float s = 0.f;
        #pragma unroll
        for (int i = 0; i < 8; i++) s += warp_part[i];
        s += fb2[0];
        float ps = sigf(s);
        g_psi[cid] = fminf(fmaxf(ps, 0.01f), 0.99f);
    }
}

// ---------------- sequential scan, value-dim split into 8 column groups ----------------
static constexpr int VS = 32;  // value columns per block (DK / 8)
static constexpr int SMEM_SCAN = (2 * DK * VS + CD + Cq * VS + Cq * Cq) * 4;  // 155648 B

__global__ __launch_bounds__(256) void scan_kernel(
    const float* __restrict__ lam_fast, const float* __restrict__ lam_slow)
{
    int g  = blockIdx.x;          // 0..7 value slice
    int bh = blockIdx.y;          // 0..15
    int h  = bh % Hq;
    int v0 = g * VS;
    int t  = threadIdx.x;
    int v  = t & 31;
    int cg = t >> 5;              // 0..7

    extern __shared__ float sm[];
    float* Sf = sm;               // [DK][VS]
    float* Ss = Sf + DK * VS;     // [DK][VS]
    float* st = Ss + DK * VS;     // staging [C][DK]
    float* su = st + CD;          // u_i [C][VS]
    float* sa = su + Cq * VS;     // attn [C][C]

    for (int i = t; i < DK * VS; i += 256) { Sf[i] = 0.f; Ss[i] = 0.f; }
    float lf = lam_fast[h], ls = lam_slow[h];

    for (int n = 0; n < NCq; n++) {
        int cid = bh * NCq + n;
        size_t base = (size_t)cid * CD;
        __syncthreads();  // protect st / Sf from previous iteration
        // stage w + attn
        for (int i = t * 4; i < CD; i += 1024)
            *(float4*)&st[i] = *(const float4*)&g_w[base + i];
        for (int i = t; i < Cq * Cq; i += 256)
            sa[i] = g_attn[(size_t)cid * Cq * Cq + i];
        __syncthreads();

        // u_i[c][v] = u[c][v] - sum_d w[c][d] * (Sf+Ss)[d][v]
        float acc[8];
        #pragma unroll
        for (int j = 0; j < 8; j++) acc[j] = g_u[base + (size_t)(cg * 8 + j) * DK + v0 + v];
        for (int d = 0; d < DK; d++) {
            float s = Sf[d * VS + v] + Ss[d * VS + v];
            #pragma unroll
            for (int j = 0; j < 8; j++) acc[j] -= st[(cg * 8 + j) * DK + d] * s;
        }
        #pragma unroll
        for (int j = 0; j < 8; j++) su[(cg * 8 + j) * VS + v] = acc[j];
        __syncthreads();

        // stage q
        for (int i = t * 4; i < CD; i += 1024)
            *(float4*)&st[i] = *(const float4*)&g_q[base + i];
        __syncthreads();

        // o = q@S + attn@u_i
        float oacc[8];
        #pragma unroll
        for (int j = 0; j < 8; j++) oacc[j] = 0.f;
        for (int d = 0; d < DK; d++) {
            float s = Sf[d * VS + v] + Ss[d * VS + v];
            #pragma unroll
            for (int j = 0; j < 8; j++) oacc[j] += st[(cg * 8 + j) * DK + d] * s;
        }
        for (int e = 0; e < Cq; e++) {
            float uev = su[e * VS + v];
            #pragma unroll
            for (int j = 0; j < 8; j++) oacc[j] += sa[(cg * 8 + j) * Cq + e] * uev;
        }
        #pragma unroll
        for (int j = 0; j < 8; j++) g_o[base + (size_t)(cg * 8 + j) * DK + v0 + v] = oacc[j];
        __syncthreads();

        // stage k
        for (int i = t * 4; i < CD; i += 1024)
            *(float4*)&st[i] = *(const float4*)&g_k[base + i];
        __syncthreads();

        // dS[d][v] = sum_c k[c][d] u_i[c][v]; state update
        float p = g_psi[cid];
        for (int dd = 0; dd < 32; dd++) {
            int d = cg * 32 + dd;
            float ds = 0.f;
            #pragma unroll 8
            for (int c = 0; c < Cq; c++) ds += st[c * DK + d] * su[c * VS + v];
            int idx = d * VS + v;
            Sf[idx] = lf * Sf[idx] + p * ds;
            Ss[idx] = ls * Ss[idx] + (1.f - p) * ds;
        }
    }
}

// ---------------- RMS-norm + gate ----------------
__global__ __launch_bounds__(256) void gate_kernel(const float* __restrict__ rms_w)
{
    int r = blockIdx.x;
    int b = r >> 12, l = r & 4095;
    int t = threadIdx.x;
    __shared__ float ms[Hq];
    if (t < 4) ms[t] = 0.f;
    __syncthreads();
    int n = l >> 6, c = l & 63;
    float ov[4];
    #pragma unroll
    for (int i = 0; i < 4; i++) {
        ov[i] = g_o[((size_t)((b * Hq + i) * NCq + n) * Cq + c) * DK + t];
        float s = ov[i] * ov[i];
        #pragma unroll
        for (int o = 16; o; o >>= 1) s += __shfl_xor_sync(~0u, s, o);
        if ((t & 31) == 0) atomicAdd(&ms[i], s);
    }
    __syncthreads();
    float rw = rms_w[t];
    #pragma unroll
    for (int i = 0; i < 4; i++) {
        float gg = g_Pg[(size_t)r * Dq + i * 256 + t];
        float val = ov[i] * rsqrtf(ms[i] * (1.f / 256.f) + 1e-5f) * rw * sigf(gg);
        g_og[(size_t)r * Dq + i * 256 + t] = val;
    }
}

// ---------------- launch ----------------
extern "C" void kernel_launch(void* const* d_in, const int* in_sizes, int n_in,
                              void* d_out, int out_size)
{
    const float* x        = (const float*)d_in[0];
    const float* Wq       = (const float*)d_in[1];
    const float* Wk       = (const float*)d_in[2];
    const float* Wv       = (const float*)d_in[3];
    const float* Wb       = (const float*)d_in[4];
    const float* Wg       = (const float*)d_in[5];
    const float* Wo       = (const float*)d_in[6];
    const float* cq       = (const float*)d_in[7];
    const float* ck       = (const float*)d_in[8];
    const float* cv       = (const float*)d_in[9];
    const float* Wbil     = (const float*)d_in[10];
    const float* temp     = (const float*)d_in[11];
    const float* fw1      = (const float*)d_in[12];
    const float* fb1      = (const float*)d_in[13];
    const float* fw2      = (const float*)d_in[14];
    const float* fb2      = (const float*)d_in[15];
    const float* rms_w    = (const float*)d_in[16];
    const float* lam_fast = (const float*)d_in[17];
    const float* lam_slow = (const float*)d_in[18];
    float* out = (float*)d_out;

    cudaFuncSetAttribute(chunk_kernel, cudaFuncAttributeMaxDynamicSharedMemorySize, SMEM_CHUNK);
    cudaFuncSetAttribute(scan_kernel,  cudaFuncAttributeMaxDynamicSharedMemorySize, SMEM_SCAN);

    float *pPq, *pPk, *pPv, *pPg, *pOg;
    cudaGetSymbolAddress((void**)&pPq, g_Pq);
    cudaGetSymbolAddress((void**)&pPk, g_Pk);
    cudaGetSymbolAddress((void**)&pPv, g_Pv);
    cudaGetSymbolAddress((void**)&pPg, g_Pg);
    cudaGetSymbolAddress((void**)&pOg, g_og);

    dim3 gg(Dq / 128, BL / 128);
    sgemm_kernel<<<gg, 256>>>(x, Wq, pPq, BL, Dq, Dq);
    sgemm_kernel<<<gg, 256>>>(x, Wk, pPk, BL, Dq, Dq);
    sgemm_kernel<<<gg, 256>>>(x, Wv, pPv, BL, Dq, Dq);
    sgemm_kernel<<<gg, 256>>>(x, Wg, pPg, BL, Dq, Dq);
    beta_kernel<<<BL, 128>>>(x, Wb);
    conv_kernel<<<BL, 256>>>(cq, ck, cv);
    chunk_kernel<<<CHUNKS, 256, SMEM_CHUNK>>>(Wbil, temp, fw1, fb1, fw2, fb2);
    scan_kernel<<<dim3(8, BH), 256, SMEM_SCAN>>>(lam_fast, lam_slow);
    gate_kernel<<<BL, 256>>>(rms_w);
    sgemm_kernel<<<gg, 256>>>(pOg, Wo, out, BL, Dq, Dq);
}

// round 17
// speedup vs baseline: 1.2025x; 1.2025x over previous
#include <cuda_runtime.h>
#include <cuda_bf16.h>
#include <cstdint>

// ---------------- problem constants ----------------
static constexpr int Bq  = 4;
static constexpr int Lq  = 4096;
static constexpr int Dq  = 1024;
static constexpr int Hq  = 4;
static constexpr int DK  = 256;
static constexpr int Cq  = 64;
static constexpr int NCq = 64;
static constexpr int KSq = 4;
static constexpr int FH  = 128;
static constexpr int BL  = Bq * Lq;       // 16384
static constexpr int BH  = Bq * Hq;       // 16
static constexpr int CHUNKS = BH * NCq;   // 1024
static constexpr int CD  = Cq * DK;       // 16384

// ---------------- scratch ----------------
__device__ float g_Pq[BL * Dq];
__device__ float g_Pk[BL * Dq];
__device__ float g_Pv[BL * Dq];
__device__ float g_Pg[BL * Dq];
__device__ float g_beta[BL * Hq];
__device__ float g_q[BL * Dq];
__device__ float g_k[BL * Dq];
__device__ float g_v[BL * Dq];
__device__ float g_w[BL * Dq];
__device__ float g_u[BL * Dq];
__device__ float g_attn[CHUNKS * Cq * Cq];
__device__ float g_psi[CHUNKS];
__device__ float g_o[BL * Dq];
__device__ float g_og[BL * Dq];

__device__ __forceinline__ float sigf(float x) { return 1.f / (1.f + expf(-x)); }

// split (a,b) fp32 -> packed bf16x2 hi + residual lo
__device__ __forceinline__ void split2(float a, float b, uint32_t& hi, uint32_t& lo) {
    __nv_bfloat16 ha = __float2bfloat16_rn(a);
    __nv_bfloat16 hb = __float2bfloat16_rn(b);
    float ra = a - __bfloat162float(ha);
    float rb = b - __bfloat162float(hb);
    __nv_bfloat162 hh = __halves2bfloat162(ha, hb);
    __nv_bfloat162 ll = __floats2bfloat162_rn(ra, rb);
    hi = reinterpret_cast<uint32_t&>(hh);
    lo = reinterpret_cast<uint32_t&>(ll);
}

__device__ __forceinline__ void mma16816(float* c, const uint32_t* a, const uint32_t* b) {
    asm volatile(
        "mma.sync.aligned.m16n8k16.row.col.f32.bf16.bf16.f32 "
        "{%0,%1,%2,%3}, {%4,%5,%6,%7}, {%8,%9}, {%0,%1,%2,%3};"
        : "+f"(c[0]), "+f"(c[1]), "+f"(c[2]), "+f"(c[3])
        : "r"(a[0]), "r"(a[1]), "r"(a[2]), "r"(a[3]), "r"(b[0]), "r"(b[1]));
}

// ===== tensor-core GEMM via mma.sync: C[M,N] = A[M,K] @ B[K,N], fp32 io =====
// 256 thr = 8 warps (4x2), CTA tile 128x128, BK=32, bf16 hi/lo split (3 products).
static constexpr int BK  = 32;
static constexpr int AST = 40;                       // smem row stride (elems), conflict-free
static constexpr int GT  = 128 * AST;                // elems per tile plane
static constexpr int SMEM_GEMM = 4 * GT * 2;         // Ah,Al,Bh,Bl bf16 = 40960 B

__global__ __launch_bounds__(256) void gemm_mma_kernel(
    const float* __restrict__ A, const float* __restrict__ B,
    float* __restrict__ C, int M, int N, int K)
{
    extern __shared__ __nv_bfloat16 smb[];
    __nv_bfloat16* Ah = smb;
    __nv_bfloat16* Al = Ah + GT;
    __nv_bfloat16* Bh = Al + GT;
    __nv_bfloat16* Bl = Bh + GT;

    const int t = threadIdx.x;
    const int w = t >> 5, lane = t & 31;
    const int bx = blockIdx.x, by = blockIdx.y;

    const float* Ab = A + (size_t)(by * 128) * K;
    const float* Bb = B + bx * 128;

    // A prefetch mapping: rows arow0 and arow0+64, k = ak..ak+7
    const int arow0 = w * 8 + (lane >> 2);
    const int ak    = (lane & 3) * 8;
    // B prefetch mapping: k rows bkg, bkg+1; cols bng..bng+7
    const int bkg = (t & 15) * 2;
    const int bng = (t >> 4) * 8;

    float4 ra[4], rb[4];

    #define LOAD_A(k0) do { \
        const float* p0 = Ab + (size_t)arow0 * K + (k0) + ak; \
        ra[0] = *(const float4*)p0; ra[1] = *(const float4*)(p0 + 4); \
        const float* p1 = p0 + (size_t)64 * K; \
        ra[2] = *(const float4*)p1; ra[3] = *(const float4*)(p1 + 4); \
    } while (0)
    #define LOAD_B(k0) do { \
        const float* p0 = Bb + (size_t)((k0) + bkg) * N + bng; \
        rb[0] = *(const float4*)p0; rb[1] = *(const float4*)(p0 + 4); \
        const float* p1 = p0 + N; \
        rb[2] = *(const float4*)p1; rb[3] = *(const float4*)(p1 + 4); \
    } while (0)

    // accumulators: 2 m-tiles x 8 n-tiles x 4
    float acc[2][8][4];
    #pragma unroll
    for (int i = 0; i < 2; i++)
        #pragma unroll
        for (int j = 0; j < 8; j++)
            #pragma unroll
            for (int x = 0; x < 4; x++) acc[i][j][x] = 0.f;

    const int wm = w & 3, wn = w >> 2;
    const int m0 = wm * 32, n0 = wn * 64;
    const int group = lane >> 2, tg = lane & 3;

    const int NKC = K / BK;
    LOAD_A(0);
    LOAD_B(0);

    for (int ch = 0; ch < NKC; ch++) {
        // ---- stage current regs -> smem (convert to bf16 hi/lo) ----
        {
            // A: 8 floats per pass
            const float* fa = (const float*)ra;
            #pragma unroll
            for (int p = 0; p < 2; p++) {
                int row = arow0 + p * 64;
                uint2 h0, l0, h1, l1;
                split2(fa[p*8+0], fa[p*8+1], h0.x, l0.x);
                split2(fa[p*8+2], fa[p*8+3], h0.y, l0.y);
                split2(fa[p*8+4], fa[p*8+5], h1.x, l1.x);
                split2(fa[p*8+6], fa[p*8+7], h1.y, l1.y);
                *(uint2*)&Ah[row * AST + ak]     = h0;
                *(uint2*)&Ah[row * AST + ak + 4] = h1;
                *(uint2*)&Al[row * AST + ak]     = l0;
                *(uint2*)&Al[row * AST + ak + 4] = l1;
            }
            // B: rb[0..1] = k row bkg, cols bng..+7 ; rb[2..3] = k row bkg+1
            const float* fb = (const float*)rb;
            #pragma unroll
            for (int i = 0; i < 8; i++) {
                uint32_t hi, lo;
                split2(fb[i], fb[8 + i], hi, lo);   // (k, k+1) pair for col bng+i
                *(uint32_t*)&Bh[(bng + i) * AST + bkg] = hi;
                *(uint32_t*)&Bl[(bng + i) * AST + bkg] = lo;
            }
        }
        __syncthreads();

        // ---- prefetch next chunk (overlaps with compute below) ----
        if (ch + 1 < NKC) {
            LOAD_A((ch + 1) * BK);
            LOAD_B((ch + 1) * BK);
        }

        // ---- compute from smem ----
        #pragma unroll
        for (int ks = 0; ks < BK; ks += 16) {
            uint32_t a_h[2][4], a_l[2][4];
            #pragma unroll
            for (int mt = 0; mt < 2; mt++) {
                int r = m0 + mt * 16 + group;
                a_h[mt][0] = *(const uint32_t*)&Ah[r * AST + ks + tg * 2];
                a_h[mt][1] = *(const uint32_t*)&Ah[(r + 8) * AST + ks + tg * 2];
                a_h[mt][2] = *(const uint32_t*)&Ah[r * AST + ks + 8 + tg * 2];
                a_h[mt][3] = *(const uint32_t*)&Ah[(r + 8) * AST + ks + 8 + tg * 2];
                a_l[mt][0] = *(const uint32_t*)&Al[r * AST + ks + tg * 2];
                a_l[mt][1] = *(const uint32_t*)&Al[(r + 8) * AST + ks + tg * 2];
                a_l[mt][2] = *(const uint32_t*)&Al[r * AST + ks + 8 + tg * 2];
                a_l[mt][3] = *(const uint32_t*)&Al[(r + 8) * AST + ks + 8 + tg * 2];
            }
            #pragma unroll
            for (int nt = 0; nt < 8; nt++) {
                int n = n0 + nt * 8 + group;
                uint32_t b_h[2], b_l[2];
                b_h[0] = *(const uint32_t*)&Bh[n * AST + ks + tg * 2];
                b_h[1] = *(const uint32_t*)&Bh[n * AST + ks + 8 + tg * 2];
                b_l[0] = *(const uint32_t*)&Bl[n * AST + ks + tg * 2];
                b_l[1] = *(const uint32_t*)&Bl[n * AST + ks + 8 + tg * 2];
                #pragma unroll
                for (int mt = 0; mt < 2; mt++) {
                    mma16816(acc[mt][nt], a_h[mt], b_h);
                    mma16816(acc[mt][nt], a_h[mt], b_l);
                    mma16816(acc[mt][nt], a_l[mt], b_h);
                }
            }
        }
        __syncthreads();
    }

    // ---- epilogue ----
    #pragma unroll
    for (int mt = 0; mt < 2; mt++) {
        int r = by * 128 + m0 + mt * 16 + group;
        #pragma unroll
        for (int nt = 0; nt < 8; nt++) {
            int c = bx * 128 + n0 + nt * 8 + tg * 2;
            *(float2*)&C[(size_t)r * N + c]       = make_float2(acc[mt][nt][0], acc[mt][nt][1]);
            *(float2*)&C[(size_t)(r + 8) * N + c] = make_float2(acc[mt][nt][2], acc[mt][nt][3]);
        }
    }
    #undef LOAD_A
    #undef LOAD_B
}

// ---------------- beta = sigmoid(x @ Wb), (BL, H) ----------------
__global__ __launch_bounds__(128) void beta_kernel(
    const float* __restrict__ x, const float* __restrict__ Wb)
{
    int r = blockIdx.x;
    int lane = threadIdx.x & 31;
    int h    = threadIdx.x >> 5;
    const float* xr = x + (size_t)r * Dq;
    float s = 0.f;
    for (int d = lane; d < Dq; d += 32) s += xr[d] * Wb[d * Hq + h];
    #pragma unroll
    for (int o = 16; o; o >>= 1) s += __shfl_xor_sync(~0u, s, o);
    if (lane == 0) g_beta[(size_t)r * Hq + h] = sigf(s);
}

// ---------------- conv + silu + l2norm(q,k) + chunk-layout scatter ----------------
__global__ __launch_bounds__(256) void conv_kernel(
    const float* __restrict__ cq, const float* __restrict__ ck, const float* __restrict__ cv)
{
    int r = blockIdx.x;
    int b = r >> 12;
    int l = r & 4095;
    int t = threadIdx.x;
    __shared__ float sums[2][Hq];
    if (t < 8) ((float*)sums)[t] = 0.f;
    __syncthreads();

    float qv[4], kv[4], vv[4];
    #pragma unroll
    for (int i = 0; i < 4; i++) {
        int d = i * 256 + t;
        float aq = 0.f, ak = 0.f, av = 0.f;
        #pragma unroll
        for (int j = 0; j < KSq; j++) {
            int ll = l - 2 + j;
            if ((unsigned)ll < (unsigned)Lq) {
                size_t idx = (size_t)(b * Lq + ll) * Dq + d;
                aq += g_Pq[idx] * cq[d * KSq + j];
                ak += g_Pk[idx] * ck[d * KSq + j];
                av += g_Pv[idx] * cv[d * KSq + j];
            }
        }
        qv[i] = aq * sigf(aq);
        kv[i] = ak * sigf(ak);
        vv[i] = av * sigf(av);
        float sq = qv[i] * qv[i];
        float sk = kv[i] * kv[i];
        #pragma unroll
        for (int o = 16; o; o >>= 1) {
            sq += __shfl_xor_sync(~0u, sq, o);
            sk += __shfl_xor_sync(~0u, sk, o);
        }
        if ((t & 31) == 0) {
            atomicAdd(&sums[0][i], sq);
            atomicAdd(&sums[1][i], sk);
        }
    }
    __syncthreads();
    int n = l >> 6, c = l & 63;
    #pragma unroll
    for (int i = 0; i < 4; i++) {
        float rq = rsqrtf(sums[0][i] + 1e-6f);
        float rk = rsqrtf(sums[1][i] + 1e-6f);
        size_t o = ((size_t)((b * Hq + i) * NCq + n) * Cq + c) * DK + t;
        g_q[o] = qv[i] * rq;
        g_k[o] = kv[i] * rk;
        g_v[o] = vv[i];
    }
}

// ---------------- per-chunk: A, T=(I+A)^-1, w, u, attn, flux MLP -> psi ----------------
static constexpr int DKP = 257;
static constexpr int SMEM_CHUNK = (2 * 64 * DKP + 2 * 64 * 65 + 64 + 520) * 4;

__global__ __launch_bounds__(256) void chunk_kernel(
    const float* __restrict__ Wbil, const float* __restrict__ temp,
    const float* __restrict__ fw1, const float* __restrict__ fb1,
    const float* __restrict__ fw2, const float* __restrict__ fb2)
{
    int cid = blockIdx.x;
    int n  = cid % NCq;
    int bh = cid / NCq;
    int h  = bh % Hq;
    int b  = bh / Hq;
    int t  = threadIdx.x;

    extern __shared__ float sm[];
    float* sk    = sm;
    float* sq    = sk + 64 * DKP;
    float* sT    = sq + 64 * DKP;
    float* sA    = sT + 64 * 65;
    float* sbeta = sA + 64 * 65;
    float* sred  = sbeta + 64;
    __shared__ float warp_part[8];

    size_t base = (size_t)cid * CD;
    for (int i = t; i < CD; i += 256) {
        int c = i >> 8, d = i & 255;
        sk[c * DKP + d] = g_k[base + i];
        sq[c * DKP + d] = g_q[base + i];
    }
    if (t < 64) sbeta[t] = g_beta[(size_t)(b * Lq + n * Cq + t) * Hq + h];
    __syncthreads();

    for (int p = t; p < 64 * 64; p += 256) {
        int i = p >> 6, j = p & 63;
        float val = 0.f;
        if (j < i) {
            const float* ki = sk + i * DKP;
            const float* kj = sk + j * DKP;
            #pragma unroll 8
            for (int d = 0; d < 256; d++) val += ki[d] * kj[d];
            val *= sbeta[i];
        }
        sA[i * 65 + j] = val;
    }
    __syncthreads();

    for (int p = t; p < 64 * 64; p += 256) {
        int i = p >> 6, j = p & 63;
        sT[i * 65 + j] = (i == j) ? 1.f : 0.f;
    }
    __syncthreads();
    for (int i = 1; i < 64; i++) {
        if (t < i) {
            float s = 0.f;
            for (int m = t; m < i; m++) s += sA[i * 65 + m] * sT[m * 65 + t];
            sT[i * 65 + t] = -s;
        }
        __syncthreads();
    }

    for (int p = t; p < 64 * 64; p += 256) {
        int i = p >> 6, j = p & 63;
        float val = 0.f;
        if (j <= i) {
            const float* qi = sq + i * DKP;
            const float* kj = sk + j * DKP;
            #pragma unroll 8
            for (int d = 0; d < 256; d++) val += qi[d] * kj[d];
        }
        g_attn[(size_t)cid * Cq * Cq + p] = val;
    }

    {
        float acc[64];
        #pragma unroll
        for (int c = 0; c < 64; c++) acc[c] = 0.f;
        for (int e = 0; e < 64; e++) {
            float kv = sbeta[e] * sk[e * DKP + t];
            #pragma unroll
            for (int c = 0; c < 64; c++) acc[c] += sT[c * 65 + e] * kv;
        }
        #pragma unroll
        for (int c = 0; c < 64; c++) g_w[base + c * DK + t] = acc[c];
    }

    float u_loc[64];
    {
        #pragma unroll
        for (int c = 0; c < 64; c++) u_loc[c] = 0.f;
        for (int e = 0; e < 64; e++) {
            float vv = sbeta[e] * g_v[base + e * DK + t];
            #pragma unroll
            for (int c = 0; c < 64; c++) u_loc[c] += sT[c * 65 + e] * vv;
        }
        #pragma unroll
        for (int c = 0; c < 64; c++) g_u[base + c * DK + t] = u_loc[c];
    }

    float avp = 0.f;
    {
        const float* Wbh = Wbil + (size_t)h * DK * DK;
        for (int d = 0; d < 256; d++) {
            float m = 0.f;
            #pragma unroll 8
            for (int c = 0; c < 64; c++) m += sk[c * DKP + d] * u_loc[c];
            avp += m * Wbh[(size_t)d * DK + t];
        }
    }
    {
        float s = avp;
        #pragma unroll
        for (int o = 16; o; o >>= 1) s += __shfl_xor_sync(~0u, s, o);
        if ((t & 31) == 0) warp_part[t >> 5] = s;
    }
    __syncthreads();
    float avg;
    {
        float s = 0.f;
        #pragma unroll
        for (int i = 0; i < 8; i++) s += warp_part[i];
        avg = s / (float)Cq / temp[h];
    }

    float km = 0.f, um = 0.f;
    #pragma unroll
    for (int c = 0; c < 64; c++) { km += sk[c * DKP + t]; um += u_loc[c]; }
    km *= (1.f / 64.f); um *= (1.f / 64.f);
    sred[t] = km; sred[256 + t] = um;
    if (t == 0) sred[512] = avg;
    __syncthreads();

    float h1v = 0.f;
    if (t < FH) {
        float s = fb1[t];
        for (int i = 0; i < 513; i++) s += sred[i] * fw1[i * FH + t];
        h1v = s * sigf(s);
    }
    float pp = (t < FH) ? h1v * fw2[t] : 0.f;
    #pragma unroll
    for (int o = 16; o; o >>= 1) pp += __shfl_xor_sync(~0u, pp, o);
    __syncthreads();
    if ((t & 31) == 0) warp_part[t >> 5] = pp;
    __syncthreads();
    if (t == 0) {
        float s = 0.f;
        #pragma unroll
        for (int i = 0; i < 8; i++) s += warp_part[i];
        s += fb2[0];
        float ps = sigf(s);
        g_psi[cid] = fminf(fmaxf(ps, 0.01f), 0.99f);
    }
}

// ---------------- sequential scan, value-dim split into 8 column groups ----------------
static constexpr int VS = 32;
static constexpr int SMEM_SCAN = (2 * DK * VS + CD + Cq * VS + Cq * Cq) * 4;

__global__ __launch_bounds__(256) void scan_kernel(
    const float* __restrict__ lam_fast, const float* __restrict__ lam_slow)
{
    int g  = blockIdx.x;
    int bh = blockIdx.y;
    int h  = bh % Hq;
    int v0 = g * VS;
    int t  = threadIdx.x;
    int v  = t & 31;
    int cg = t >> 5;

    extern __shared__ float sm[];
    float* Sf = sm;
    float* Ss = Sf + DK * VS;
    float* st = Ss + DK * VS;
    float* su = st + CD;
    float* sa = su + Cq * VS;

    for (int i = t; i < DK * VS; i += 256) { Sf[i] = 0.f; Ss[i] = 0.f; }
    float lf = lam_fast[h], ls = lam_slow[h];

    for (int n = 0; n < NCq; n++) {
        int cid = bh * NCq + n;
        size_t base = (size_t)cid * CD;
        __syncthreads();
        for (int i = t * 4; i < CD; i += 1024)
            *(float4*)&st[i] = *(const float4*)&g_w[base + i];
        for (int i = t; i < Cq * Cq; i += 256)
            sa[i] = g_attn[(size_t)cid * Cq * Cq + i];
        __syncthreads();

        float acc[8];
        #pragma unroll
        for (int j = 0; j < 8; j++) acc[j] = g_u[base + (size_t)(cg * 8 + j) * DK + v0 + v];
        for (int d = 0; d < DK; d++) {
            float s = Sf[d * VS + v] + Ss[d * VS + v];
            #pragma unroll
            for (int j = 0; j < 8; j++) acc[j] -= st[(cg * 8 + j) * DK + d] * s;
        }
        #pragma unroll
        for (int j = 0; j < 8; j++) su[(cg * 8 + j) * VS + v] = acc[j];
        __syncthreads();

        for (int i = t * 4; i < CD; i += 1024)
            *(float4*)&st[i] = *(const float4*)&g_q[base + i];
        __syncthreads();

        float oacc[8];
        #pragma unroll
        for (int j = 0; j < 8; j++) oacc[j] = 0.f;
        for (int d = 0; d < DK; d++) {
            float s = Sf[d * VS + v] + Ss[d * VS + v];
            #pragma unroll
            for (int j = 0; j < 8; j++) oacc[j] += st[(cg * 8 + j) * DK + d] * s;
        }
        for (int e = 0; e < Cq; e++) {
            float uev = su[e * VS + v];
            #pragma unroll
            for (int j = 0; j < 8; j++) oacc[j] += sa[(cg * 8 + j) * Cq + e] * uev;
        }
        #pragma unroll
        for (int j = 0; j < 8; j++) g_o[base + (size_t)(cg * 8 + j) * DK + v0 + v] = oacc[j];
        __syncthreads();

        for (int i = t * 4; i < CD; i += 1024)
            *(float4*)&st[i] = *(const float4*)&g_k[base + i];
        __syncthreads();

        float p = g_psi[cid];
        for (int dd = 0; dd < 32; dd++) {
            int d = cg * 32 + dd;
            float ds = 0.f;
            #pragma unroll 8
            for (int c = 0; c < Cq; c++) ds += st[c * DK + d] * su[c * VS + v];
            int idx = d * VS + v;
            Sf[idx] = lf * Sf[idx] + p * ds;
            Ss[idx] = ls * Ss[idx] + (1.f - p) * ds;
        }
    }
}

// ---------------- RMS-norm + gate ----------------
__global__ __launch_bounds__(256) void gate_kernel(const float* __restrict__ rms_w)
{
    int r = blockIdx.x;
    int b = r >> 12, l = r & 4095;
    int t = threadIdx.x;
    __shared__ float ms[Hq];
    if (t < 4) ms[t] = 0.f;
    __syncthreads();
    int n = l >> 6, c = l & 63;
    float ov[4];
    #pragma unroll
    for (int i = 0; i < 4; i++) {
        ov[i] = g_o[((size_t)((b * Hq + i) * NCq + n) * Cq + c) * DK + t];
        float s = ov[i] * ov[i];
        #pragma unroll
        for (int o = 16; o; o >>= 1) s += __shfl_xor_sync(~0u, s, o);
        if ((t & 31) == 0) atomicAdd(&ms[i], s);
    }
    __syncthreads();
    float rw = rms_w[t];
    #pragma unroll
    for (int i = 0; i < 4; i++) {
        float gg = g_Pg[(size_t)r * Dq + i * 256 + t];
        float val = ov[i] * rsqrtf(ms[i] * (1.f / 256.f) + 1e-5f) * rw * sigf(gg);
        g_og[(size_t)r * Dq + i * 256 + t] = val;
    }
}

// ---------------- launch ----------------
extern "C" void kernel_launch(void* const* d_in, const int* in_sizes, int n_in,
                              void* d_out, int out_size)
{
    const float* x        = (const float*)d_in[0];
    const float* Wq       = (const float*)d_in[1];
    const float* Wk       = (const float*)d_in[2];
    const float* Wv       = (const float*)d_in[3];
    const float* Wb       = (const float*)d_in[4];
    const float* Wg       = (const float*)d_in[5];
    const float* Wo       = (const float*)d_in[6];
    const float* cq       = (const float*)d_in[7];
    const float* ck       = (const float*)d_in[8];
    const float* cv       = (const float*)d_in[9];
    const float* Wbil     = (const float*)d_in[10];
    const float* temp     = (const float*)d_in[11];
    const float* fw1      = (const float*)d_in[12];
    const float* fb1      = (const float*)d_in[13];
    const float* fw2      = (const float*)d_in[14];
    const float* fb2      = (const float*)d_in[15];
    const float* rms_w    = (const float*)d_in[16];
    const float* lam_fast = (const float*)d_in[17];
    const float* lam_slow = (const float*)d_in[18];
    float* out = (float*)d_out;

    cudaFuncSetAttribute(chunk_kernel, cudaFuncAttributeMaxDynamicSharedMemorySize, SMEM_CHUNK);
    cudaFuncSetAttribute(scan_kernel,  cudaFuncAttributeMaxDynamicSharedMemorySize, SMEM_SCAN);

    float *pPq, *pPk, *pPv, *pPg, *pOg;
    cudaGetSymbolAddress((void**)&pPq, g_Pq);
    cudaGetSymbolAddress((void**)&pPk, g_Pk);
    cudaGetSymbolAddress((void**)&pPv, g_Pv);
    cudaGetSymbolAddress((void**)&pPg, g_Pg);
    cudaGetSymbolAddress((void**)&pOg, g_og);

    dim3 gg(Dq / 128, BL / 128);
    gemm_mma_kernel<<<gg, 256, SMEM_GEMM>>>(x, Wq, pPq, BL, Dq, Dq);
    gemm_mma_kernel<<<gg, 256, SMEM_GEMM>>>(x, Wk, pPk, BL, Dq, Dq);
    gemm_mma_kernel<<<gg, 256, SMEM_GEMM>>>(x, Wv, pPv, BL, Dq, Dq);
    gemm_mma_kernel<<<gg, 256, SMEM_GEMM>>>(x, Wg, pPg, BL, Dq, Dq);
    beta_kernel<<<BL, 128>>>(x, Wb);
    conv_kernel<<<BL, 256>>>(cq, ck, cv);
    chunk_kernel<<<CHUNKS, 256, SMEM_CHUNK>>>(Wbil, temp, fw1, fb1, fw2, fb2);
    scan_kernel<<<dim3(8, BH), 256, SMEM_SCAN>>>(lam_fast, lam_slow);
    gate_kernel<<<BL, 256>>>(rms_w);
    gemm_mma_kernel<<<gg, 256, SMEM_GEMM>>>(pOg, Wo, out, BL, Dq, Dq);
}